// round 3
// baseline (speedup 1.0000x reference)
#include <cuda_runtime.h>
#include <cuda_bf16.h>
#include <cstdint>

#define BB   128
#define TT   256
#define NN   100
#define SS   7
#define GG   16
#define FF   35
#define FP   36   // padded H1 row stride in lm kernel

typedef unsigned long long ull;

// gi scratch: [n][t][b][48] fp32  (629 MB)
__device__ float g_gi[(size_t)NN * TT * BB * 48];

__device__ __forceinline__ ull fma2(ull a, ull b, ull c) {
    ull d; asm("fma.rn.f32x2 %0, %1, %2, %3;" : "=l"(d) : "l"(a), "l"(b), "l"(c));
    return d;
}
__device__ __forceinline__ ull dup2(float w) {
    ull d; asm("mov.b64 %0, {%1, %1};" : "=l"(d) : "f"(w));
    return d;
}
__device__ __forceinline__ float plo(ull p) { return __int_as_float((int)(unsigned)p); }
__device__ __forceinline__ float phi(ull p) { return __int_as_float((int)(p >> 32)); }

__device__ __forceinline__ float sigf(float x) {
    return __fdividef(1.0f, 1.0f + __expf(-x));
}
__device__ __forceinline__ float tanhfast(float x) {
    return __fdividef(2.0f, 1.0f + __expf(-2.0f * x)) - 1.0f;
}

// ============================================================================
// Kernel A: gi GEMM.  gi[n][t][b][g48] = sum_f Wih[n][g][f] * xgathered[b][t][n][f]
// grid (128 tchunks, 100 n), 256 threads. Thread tile: 6 gates x 8 batches.
// ============================================================================
__global__ void __launch_bounds__(256) gi_gemm_kernel(
    const float* __restrict__ x,
    const float* __restrict__ Wih)
{
    __shared__ __align__(16) float xs[2][FF][BB];   // 35.8 KB
    __shared__ __align__(16) ull  wd[FF][48];       // 13.4 KB (dup'd pairs)

    const int n   = blockIdx.y;
    const int t0  = blockIdx.x * 2;
    const int tid = threadIdx.x;

    // stage weights, duplicated into pairs: Wih layout [n][g][f]
    const float* Wg = Wih + (size_t)n * 48 * FF;
    for (int i = tid; i < 48 * FF; i += 256) {
        int g = i / FF, f = i % FF;
        wd[f][g] = dup2(Wg[i]);
    }

    // stage gathered x for 2 timesteps, coalesced-ish (7 lanes share a 28B row)
    const int offs[5] = {0, -10, 1, 10, -1};
    if (tid < 224) {
        int s = tid % 7;
        int q = tid / 7;   // 0..31
        #pragma unroll
        for (int o = 0; o < 5; o++) {
            int n2 = n + offs[o];
            bool v = (n2 >= 0) && (n2 < NN);
            #pragma unroll
            for (int bc = 0; bc < 4; bc++) {
                int b = bc * 32 + q;
                const float* bp = x + ((size_t)b * TT + t0) * (NN * SS)
                                    + (v ? n2 * SS + s : 0);
                xs[0][o * 7 + s][b] = v ? bp[0] : 0.0f;
                xs[1][o * 7 + s][b] = v ? bp[NN * SS] : 0.0f;
            }
        }
    }
    __syncthreads();

    // compute: thread = (tt, gg of 6 gates, bpg of 4 b-pairs)
    const int tt  = tid >> 7;
    const int gg  = (tid >> 4) & 7;
    const int bpg = tid & 15;

    ull acc[6][4];
    #pragma unroll
    for (int g = 0; g < 6; g++)
        #pragma unroll
        for (int p = 0; p < 4; p++) acc[g][p] = 0ULL;

    #pragma unroll 5
    for (int f = 0; f < FF; f++) {
        const ull* xp = reinterpret_cast<const ull*>(&xs[tt][f][bpg * 8]);
        ull x0 = xp[0], x1 = xp[1], x2 = xp[2], x3 = xp[3];
        const ull* wp = &wd[f][gg * 6];
        #pragma unroll
        for (int g = 0; g < 6; g++) {
            ull wv = wp[g];
            acc[g][0] = fma2(x0, wv, acc[g][0]);
            acc[g][1] = fma2(x1, wv, acc[g][1]);
            acc[g][2] = fma2(x2, wv, acc[g][2]);
            acc[g][3] = fma2(x3, wv, acc[g][3]);
        }
    }
    __syncthreads();

    // transpose through smem (reuse xs) and store coalesced as [b][48]
    float* osm = &xs[0][0][0];   // 128*48 floats = 24KB <= xs
    #pragma unroll
    for (int tp = 0; tp < 2; tp++) {
        if (tt == tp) {
            #pragma unroll
            for (int g = 0; g < 6; g++)
                #pragma unroll
                for (int p = 0; p < 4; p++) {
                    int b = bpg * 8 + p * 2;
                    osm[(b    ) * 48 + gg * 6 + g] = plo(acc[g][p]);
                    osm[(b + 1) * 48 + gg * 6 + g] = phi(acc[g][p]);
                }
        }
        __syncthreads();
        float4* dst = reinterpret_cast<float4*>(
            g_gi + (((size_t)n * TT + t0 + tp) * BB) * 48);
        const float4* src = reinterpret_cast<const float4*>(osm);
        for (int i = tid; i < BB * 48 / 4; i += 256) dst[i] = src[i];
        __syncthreads();
    }
}

// ============================================================================
// Kernel C: recurrence + sc MLP. grid (16 bblk of 8 batches, 100 n), 128 thr.
// Warp w owns 2 batches; lane = (j in 16, bh in 2). Whh in registers (k-pairs).
// ============================================================================
__global__ void __launch_bounds__(128) gru_rec_kernel(
    const float* __restrict__ Whh,
    const float* __restrict__ bih, const float* __restrict__ bhh,
    const float* __restrict__ scW1, const float* __restrict__ scb1,
    const float* __restrict__ scW2, const float* __restrict__ scb2,
    const float* __restrict__ scW3, const float* __restrict__ scb3,
    float* __restrict__ out)
{
    __shared__ __align__(16) float shf[4][2][2][16];  // [warp][buf][bh][k]

    const int n    = blockIdx.y;
    const int bblk = blockIdx.x;
    const int tid  = threadIdx.x;
    const int w    = tid >> 5;
    const int lane = tid & 31;
    const int j    = lane & 15;
    const int bh   = lane >> 4;
    const int bglob = bblk * 8 + w * 2 + bh;

    // Whh rows j, j+16, j+32 as k-pair ulls (rows are 64B-aligned)
    const ull* wrp = reinterpret_cast<const ull*>(Whh + ((size_t)n * 48 + j     ) * GG);
    const ull* wzp = reinterpret_cast<const ull*>(Whh + ((size_t)n * 48 + j + 16) * GG);
    const ull* wnp = reinterpret_cast<const ull*>(Whh + ((size_t)n * 48 + j + 32) * GG);
    ull wr[8], wz[8], wn[8];
    #pragma unroll
    for (int k = 0; k < 8; k++) { wr[k] = wrp[k]; wz[k] = wzp[k]; wn[k] = wnp[k]; }

    const float br  = bih[n * 48 + j     ] + bhh[n * 48 + j     ];
    const float bz  = bih[n * 48 + j + 16] + bhh[n * 48 + j + 16];
    const float bin = bih[n * 48 + j + 32];
    const float bhn = bhh[n * 48 + j + 32];

    shf[w][0][bh][j] = 0.0f;
    float hreg = 0.0f;
    __syncwarp();

    const float* gbase = g_gi + ((size_t)n * TT * BB + bglob) * 48;
    int cur = 0;
    for (int t = 0; t < TT; t++) {
        const float* gr = gbase + (size_t)t * BB * 48;
        float gir = gr[j], giz = gr[j + 16], gin = gr[j + 32];

        const ull* hp = reinterpret_cast<const ull*>(&shf[w][cur][bh][0]);
        ull ar = 0ULL, az = 0ULL, an = 0ULL;
        #pragma unroll
        for (int k = 0; k < 8; k++) {
            ull hk = hp[k];
            ar = fma2(hk, wr[k], ar);
            az = fma2(hk, wz[k], az);
            an = fma2(hk, wn[k], an);
        }
        float r  = sigf(br + gir + plo(ar) + phi(ar));
        float z  = sigf(bz + giz + plo(az) + phi(az));
        float nv = tanhfast(bin + gin + r * (bhn + plo(an) + phi(an)));
        float hnew = nv + z * (hreg - nv);
        hreg = hnew;
        shf[w][cur ^ 1][bh][j] = hnew;
        __syncwarp();
        cur ^= 1;
    }

    // sc MLP epilogue (per warp, per batch)
    shf[w][0][bh][j] = hreg;
    __syncwarp();
    {
        float a = scb1[n * GG + j];
        #pragma unroll
        for (int k = 0; k < GG; k++)
            a = fmaf(shf[w][0][bh][k], scW1[((size_t)n * GG + k) * GG + j], a);
        shf[w][1][bh][j] = fmaxf(a, 0.0f);
    }
    __syncwarp();
    {
        float a = scb2[n * GG + j];
        #pragma unroll
        for (int k = 0; k < GG; k++)
            a = fmaf(shf[w][1][bh][k], scW2[((size_t)n * GG + k) * GG + j], a);
        shf[w][0][bh][j] = fmaxf(a, 0.0f);
    }
    __syncwarp();
    if (j == 0) {
        float q = scb3[n];
        #pragma unroll
        for (int k = 0; k < GG; k++)
            q = fmaf(shf[w][0][bh][k], scW3[n * GG + k], q);
        int idx = n * BB + bglob;
        out[idx] = out[idx] + q;   // lm kernel already wrote f
    }
}

// ============================================================================
// Kernel B: lm MLP on xl = gather(x[:, T-1]) -> WRITES f into out[n*B + b]
// grid (4 b-blocks of 32, 100 nodes), 256 threads. dyn smem: H1T [512][36].
// ============================================================================
__global__ void __launch_bounds__(256) lm_mlp_kernel(
    const float* __restrict__ x,
    const float* __restrict__ W1, const float* __restrict__ b1,
    const float* __restrict__ W2, const float* __restrict__ b2,
    const float* __restrict__ W3, const float* __restrict__ b3,
    float* __restrict__ out)
{
    extern __shared__ __align__(16) float H1T[];      // [512][36]
    __shared__ __align__(16) float xlsT[FF][32];
    __shared__ __align__(16) float H2s[32][257];
    __shared__ float sp[8][32];

    const int n    = blockIdx.y;
    const int bblk = blockIdx.x;
    const int tid  = threadIdx.x;
    const int offs[5] = {0, -10, 1, 10, -1};

    // gather xl (t = T-1), transposed [f][b]
    for (int idx = tid; idx < FF * 32; idx += 256) {
        int f = idx / 32, b = idx % 32;
        int o = f / SS, s = f % SS;
        int n2 = n + offs[o];
        float v = 0.0f;
        if (n2 >= 0 && n2 < NN) {
            size_t gb = (size_t)(bblk * 32 + b);
            v = x[(gb * TT + (TT - 1)) * (NN * SS) + n2 * SS + s];
        }
        xlsT[f][b] = v;
    }
    __syncthreads();

    // layer 1: (32x35)@(35x512) -> H1T relu. Thread tile 8h x 8b (f32x2).
    {
        const float* W1g = W1 + (size_t)n * FF * 512;
        const float* b1g = b1 + (size_t)n * 512;
        const int bg = tid >> 6;   // 4 groups of 8 batches
        const int hg = tid & 63;   // 64 groups of 8 h
        ull acc[8][4];
        #pragma unroll
        for (int h = 0; h < 8; h++)
            #pragma unroll
            for (int p = 0; p < 4; p++) acc[h][p] = 0ULL;
        #pragma unroll 5
        for (int f = 0; f < FF; f++) {
            const float4* wv = reinterpret_cast<const float4*>(W1g + f * 512 + hg * 8);
            float4 wa = wv[0], wb = wv[1];
            ull wdp[8] = {dup2(wa.x), dup2(wa.y), dup2(wa.z), dup2(wa.w),
                          dup2(wb.x), dup2(wb.y), dup2(wb.z), dup2(wb.w)};
            const ull* xp = reinterpret_cast<const ull*>(&xlsT[f][bg * 8]);
            ull x0 = xp[0], x1 = xp[1], x2 = xp[2], x3 = xp[3];
            #pragma unroll
            for (int h = 0; h < 8; h++) {
                acc[h][0] = fma2(x0, wdp[h], acc[h][0]);
                acc[h][1] = fma2(x1, wdp[h], acc[h][1]);
                acc[h][2] = fma2(x2, wdp[h], acc[h][2]);
                acc[h][3] = fma2(x3, wdp[h], acc[h][3]);
            }
        }
        #pragma unroll
        for (int h = 0; h < 8; h++) {
            float bias = b1g[hg * 8 + h];
            float* row = &H1T[(hg * 8 + h) * FP + bg * 8];
            float4 v0, v1;
            v0.x = fmaxf(plo(acc[h][0]) + bias, 0.0f);
            v0.y = fmaxf(phi(acc[h][0]) + bias, 0.0f);
            v0.z = fmaxf(plo(acc[h][1]) + bias, 0.0f);
            v0.w = fmaxf(phi(acc[h][1]) + bias, 0.0f);
            v1.x = fmaxf(plo(acc[h][2]) + bias, 0.0f);
            v1.y = fmaxf(phi(acc[h][2]) + bias, 0.0f);
            v1.z = fmaxf(plo(acc[h][3]) + bias, 0.0f);
            v1.w = fmaxf(phi(acc[h][3]) + bias, 0.0f);
            reinterpret_cast<float4*>(row)[0] = v0;
            reinterpret_cast<float4*>(row)[1] = v1;
        }
    }
    __syncthreads();

    // layer 2: (32x512)@(512x256) -> H2 relu. f32x2: 4h x 8b tile.
    {
        const float4* W2g = reinterpret_cast<const float4*>(W2 + (size_t)n * 512 * 256);
        const float*  b2g = b2 + (size_t)n * 256;
        const int hg = tid & 63;
        const int bg = tid >> 6;
        ull acc[16];
        #pragma unroll
        for (int i = 0; i < 16; i++) acc[i] = 0ULL;
        #pragma unroll 2
        for (int f = 0; f < 512; f++) {
            float4 wv = W2g[f * 64 + hg];
            ull wdp[4] = {dup2(wv.x), dup2(wv.y), dup2(wv.z), dup2(wv.w)};
            const ull* xp = reinterpret_cast<const ull*>(&H1T[f * FP + bg * 8]);
            ull x0 = xp[0], x1 = xp[1], x2 = xp[2], x3 = xp[3];
            #pragma unroll
            for (int hh = 0; hh < 4; hh++) {
                acc[hh*4+0] = fma2(x0, wdp[hh], acc[hh*4+0]);
                acc[hh*4+1] = fma2(x1, wdp[hh], acc[hh*4+1]);
                acc[hh*4+2] = fma2(x2, wdp[hh], acc[hh*4+2]);
                acc[hh*4+3] = fma2(x3, wdp[hh], acc[hh*4+3]);
            }
        }
        #pragma unroll
        for (int hh = 0; hh < 4; hh++) {
            float bias = b2g[hg * 4 + hh];
            #pragma unroll
            for (int pi = 0; pi < 4; pi++) {
                int b = bg * 8 + pi * 2;
                H2s[b    ][hg * 4 + hh] = fmaxf(plo(acc[hh*4+pi]) + bias, 0.0f);
                H2s[b + 1][hg * 4 + hh] = fmaxf(phi(acc[hh*4+pi]) + bias, 0.0f);
            }
        }
    }
    __syncthreads();

    // layer 3: (32x256)@(256x1)
    {
        const float* W3g = W3 + (size_t)n * 256;
        int b = tid & 31, seg = tid >> 5;
        float s = 0.0f;
        #pragma unroll
        for (int c = 0; c < 32; c++)
            s = fmaf(H2s[b][seg * 32 + c], W3g[seg * 32 + c], s);
        sp[seg][b] = s;
    }
    __syncthreads();
    if (tid < 32) {
        float tot = b3[n];
        #pragma unroll
        for (int seg = 0; seg < 8; seg++) tot += sp[seg][tid];
        out[n * BB + bblk * 32 + tid] = tot;
    }
}

// ============================================================================
extern "C" void kernel_launch(void* const* d_in, const int* in_sizes, int n_in,
                              void* d_out, int out_size) {
    const float* x      = (const float*)d_in[0];
    const float* lm_W1  = (const float*)d_in[1];
    const float* lm_b1  = (const float*)d_in[2];
    const float* lm_W2  = (const float*)d_in[3];
    const float* lm_b2  = (const float*)d_in[4];
    const float* lm_W3  = (const float*)d_in[5];
    const float* lm_b3  = (const float*)d_in[6];
    const float* gWih   = (const float*)d_in[7];
    const float* gWhh   = (const float*)d_in[8];
    const float* gbih   = (const float*)d_in[9];
    const float* gbhh   = (const float*)d_in[10];
    const float* scW1   = (const float*)d_in[11];
    const float* scb1   = (const float*)d_in[12];
    const float* scW2   = (const float*)d_in[13];
    const float* scb2   = (const float*)d_in[14];
    const float* scW3   = (const float*)d_in[15];
    const float* scb3   = (const float*)d_in[16];
    float* out = (float*)d_out;

    const int h1t_bytes = 512 * FP * 4;  // 73728
    cudaFuncSetAttribute(lm_mlp_kernel,
                         cudaFuncAttributeMaxDynamicSharedMemorySize, h1t_bytes);

    // A: gi GEMM (no dependencies)
    dim3 gridA(TT / 2, NN), blockA(256);
    gi_gemm_kernel<<<gridA, blockA>>>(x, gWih);

    // B: lm MLP (writes out)
    dim3 gridB(4, NN), blockB(256);
    lm_mlp_kernel<<<gridB, blockB, h1t_bytes>>>(
        x, lm_W1, lm_b1, lm_W2, lm_b2, lm_W3, lm_b3, out);

    // C: recurrence (reads gi, adds to out)
    dim3 gridC(16, NN), blockC(128);
    gru_rec_kernel<<<gridC, blockC>>>(
        gWhh, gbih, gbhh,
        scW1, scb1, scW2, scb2, scW3, scb3, out);
}

// round 4
// speedup vs baseline: 1.3534x; 1.3534x over previous
#include <cuda_runtime.h>
#include <cuda_bf16.h>
#include <cstdint>

#define BB   128
#define TT   256
#define NN   100
#define SS   7
#define GG   16
#define FF   35
#define FP   36   // padded H1 row stride in lm kernel

typedef unsigned long long ull;

// gi scratch: [n][t][b][48] fp32  (629 MB)
__device__ float g_gi[(size_t)NN * TT * BB * 48];

__device__ __forceinline__ ull fma2(ull a, ull b, ull c) {
    ull d; asm("fma.rn.f32x2 %0, %1, %2, %3;" : "=l"(d) : "l"(a), "l"(b), "l"(c));
    return d;
}
__device__ __forceinline__ ull dup2(float w) {
    ull d; asm("mov.b64 %0, {%1, %1};" : "=l"(d) : "f"(w));
    return d;
}
__device__ __forceinline__ float plo(ull p) { return __int_as_float((int)(unsigned)p); }
__device__ __forceinline__ float phi(ull p) { return __int_as_float((int)(p >> 32)); }

__device__ __forceinline__ float sigf(float x) {
    return __fdividef(1.0f, 1.0f + __expf(-x));
}
__device__ __forceinline__ float tanhfast(float x) {
    return __fdividef(2.0f, 1.0f + __expf(-2.0f * x)) - 1.0f;
}

__device__ __forceinline__ void cpasync4(uint32_t saddr, const float* gptr, int vbytes) {
    asm volatile("cp.async.ca.shared.global [%0], [%1], 4, %2;"
                 :: "r"(saddr), "l"(gptr), "r"(vbytes));
}
__device__ __forceinline__ void cpcommit() {
    asm volatile("cp.async.commit_group;");
}
__device__ __forceinline__ void cpwait0() {
    asm volatile("cp.async.wait_group 0;");
}

// ============================================================================
// Kernel A: gi GEMM.  gi[n][t][b][g48] = sum_f Wih[n][g][f] * xg[b][t][n][f]
// grid (16 tchunks of 16t, 100 n), 128 threads = 8 gg(6 gates) x 16 bpg(8 b).
// Weights staged once per block. cp.async double-buffered x staging.
// ============================================================================
#define ACH 16            // timesteps per block
#define XROW 130          // padded xs row (floats)
#define OROW 52           // padded osm row (floats), 16B-aligned

__global__ void __launch_bounds__(128) gi_gemm_kernel(
    const float* __restrict__ x,
    const float* __restrict__ Wih)
{
    extern __shared__ __align__(16) float smraw[];
    float* wd  = smraw;                       // [35][48]
    float* xs  = wd + 35 * 48;                // [2][35][XROW]
    float* osm = xs + 2 * 35 * XROW;          // [128][OROW]

    const int n   = blockIdx.y;
    const int tc  = blockIdx.x;
    const int t0  = tc * ACH;
    const int tid = threadIdx.x;
    const int gg  = tid >> 4;     // 0..7  (6 gates each)
    const int bpg = tid & 15;     // 0..15 (8 batches: pairs (b,b+1), p in 0..3)

    // ---- stage weights once: Wih[n][g][f] -> wd[f*48 + g] ----
    const float* Wg = Wih + (size_t)n * 48 * FF;
    for (int i = tid; i < 48 * FF; i += 128)
        wd[(i % FF) * 48 + (i / FF)] = Wg[i];

    // ---- staging slots: thread (s = tid%7, q = tid/7 in 0..15), 112 active ----
    const int offs[5] = {0, -10, 1, 10, -1};
    const int s  = tid % 7;
    const int q  = tid / 7;
    const bool active = (q < 16);
    int  nofs[5]; int vbytes[5];
    #pragma unroll
    for (int o = 0; o < 5; o++) {
        int n2 = n + offs[o];
        bool v = (n2 >= 0) && (n2 < NN);
        nofs[o]   = (v ? n2 : 0) * SS + s;
        vbytes[o] = v ? 4 : 0;
    }
    uint32_t xs_base = (uint32_t)__cvta_generic_to_shared(xs);

    // stage one timestep into buffer `buf`
    auto stage = [&](int buf, int t) {
        if (active) {
            #pragma unroll
            for (int o = 0; o < 5; o++) {
                int f = o * 7 + s;
                #pragma unroll
                for (int bc = 0; bc < 8; bc++) {
                    int b = bc * 16 + q;
                    const float* gp = x + (size_t)b * (TT * NN * SS)
                                        + (size_t)t * (NN * SS) + nofs[o];
                    uint32_t sa = xs_base + (uint32_t)((buf * 35 * XROW + f * XROW + b) * 4);
                    cpasync4(sa, gp, vbytes[o]);
                }
            }
        }
        cpcommit();
    };

    stage(0, t0);
    cpwait0();
    __syncthreads();

    for (int tt = 0; tt < ACH; tt++) {
        const int t   = t0 + tt;
        const int cur = tt & 1;

        // prefetch next timestep (empty group on last iter keeps counts aligned)
        if (tt < ACH - 1) stage(cur ^ 1, t + 1);
        else cpcommit();

        // ---- compute 48g x 128b for timestep t ----
        const float* xc = xs + cur * 35 * XROW;
        ull acc[6][4];
        #pragma unroll
        for (int g = 0; g < 6; g++)
            #pragma unroll
            for (int p = 0; p < 4; p++) acc[g][p] = 0ULL;

        #pragma unroll 5
        for (int f = 0; f < FF; f++) {
            const ull* xp = reinterpret_cast<const ull*>(&xc[f * XROW]);
            ull x0 = xp[bpg     ];
            ull x1 = xp[bpg + 16];
            ull x2 = xp[bpg + 32];
            ull x3 = xp[bpg + 48];
            const float* wp = &wd[f * 48 + gg * 6];
            #pragma unroll
            for (int g = 0; g < 6; g++) {
                ull wv = dup2(wp[g]);
                acc[g][0] = fma2(x0, wv, acc[g][0]);
                acc[g][1] = fma2(x1, wv, acc[g][1]);
                acc[g][2] = fma2(x2, wv, acc[g][2]);
                acc[g][3] = fma2(x3, wv, acc[g][3]);
            }
        }

        // ---- transpose via osm: osm[b][j] (row pad 52) ----
        #pragma unroll
        for (int p = 0; p < 4; p++) {
            int b = 2 * bpg + 32 * p;
            float* r0 = &osm[(size_t)b * OROW + gg * 6];
            float* r1 = r0 + OROW;
            #pragma unroll
            for (int g = 0; g < 6; g += 2) {
                float2 vlo = make_float2(plo(acc[g][p]), plo(acc[g + 1][p]));
                float2 vhi = make_float2(phi(acc[g][p]), phi(acc[g + 1][p]));
                *reinterpret_cast<float2*>(r0 + g) = vlo;
                *reinterpret_cast<float2*>(r1 + g) = vhi;
            }
        }
        __syncthreads();

        // ---- coalesced copy osm -> gi[n][t][b][48] ----
        float4* dst = reinterpret_cast<float4*>(
            g_gi + ((size_t)n * TT + t) * BB * 48);
        #pragma unroll
        for (int jv = 0; jv < 12; jv++) {
            int idx = tid + 128 * jv;            // 0..1535 float4 slots
            int b = idx / 12, c = idx % 12;
            dst[idx] = *reinterpret_cast<const float4*>(&osm[(size_t)b * OROW + c * 4]);
        }

        cpwait0();            // prefetch complete
        __syncthreads();      // osm free + xs[cur^1] visible
    }
}

// ============================================================================
// Kernel C: recurrence + sc MLP. grid (16 bblk of 8 batches, 100 n), 128 thr.
// Warp w owns 2 batches; lane = (j in 16, bh in 2). Whh in regs, gi prefetched.
// ============================================================================
__global__ void __launch_bounds__(128) gru_rec_kernel(
    const float* __restrict__ Whh,
    const float* __restrict__ bih, const float* __restrict__ bhh,
    const float* __restrict__ scW1, const float* __restrict__ scb1,
    const float* __restrict__ scW2, const float* __restrict__ scb2,
    const float* __restrict__ scW3, const float* __restrict__ scb3,
    float* __restrict__ out)
{
    __shared__ __align__(16) float shf[4][2][2][16];  // [warp][buf][bh][k]

    const int n    = blockIdx.y;
    const int bblk = blockIdx.x;
    const int tid  = threadIdx.x;
    const int w    = tid >> 5;
    const int lane = tid & 31;
    const int j    = lane & 15;
    const int bh   = lane >> 4;
    const int bglob = bblk * 8 + w * 2 + bh;

    const ull* wrp = reinterpret_cast<const ull*>(Whh + ((size_t)n * 48 + j     ) * GG);
    const ull* wzp = reinterpret_cast<const ull*>(Whh + ((size_t)n * 48 + j + 16) * GG);
    const ull* wnp = reinterpret_cast<const ull*>(Whh + ((size_t)n * 48 + j + 32) * GG);
    ull wr[8], wz[8], wn[8];
    #pragma unroll
    for (int k = 0; k < 8; k++) { wr[k] = wrp[k]; wz[k] = wzp[k]; wn[k] = wnp[k]; }

    const float br  = bih[n * 48 + j     ] + bhh[n * 48 + j     ];
    const float bz  = bih[n * 48 + j + 16] + bhh[n * 48 + j + 16];
    const float bin = bih[n * 48 + j + 32];
    const float bhn = bhh[n * 48 + j + 32];

    shf[w][0][bh][j] = 0.0f;
    float hreg = 0.0f;
    __syncwarp();

    const float* gbase = g_gi + ((size_t)n * TT * BB + bglob) * 48;
    float gir = gbase[j], giz = gbase[j + 16], gin = gbase[j + 32];

    int cur = 0;
    for (int t = 0; t < TT; t++) {
        // prefetch next t (clamped) — hides DRAM latency behind compute
        const float* grn = gbase + (size_t)((t + 1 < TT) ? t + 1 : t) * BB * 48;
        float pgr = grn[j], pgz = grn[j + 16], pgn = grn[j + 32];

        const ull* hp = reinterpret_cast<const ull*>(&shf[w][cur][bh][0]);
        ull ar = 0ULL, az = 0ULL, an = 0ULL;
        #pragma unroll
        for (int k = 0; k < 8; k++) {
            ull hk = hp[k];
            ar = fma2(hk, wr[k], ar);
            az = fma2(hk, wz[k], az);
            an = fma2(hk, wn[k], an);
        }
        float r  = sigf(br + gir + plo(ar) + phi(ar));
        float z  = sigf(bz + giz + plo(az) + phi(az));
        float nv = tanhfast(bin + gin + r * (bhn + plo(an) + phi(an)));
        float hnew = nv + z * (hreg - nv);
        hreg = hnew;
        shf[w][cur ^ 1][bh][j] = hnew;
        __syncwarp();
        gir = pgr; giz = pgz; gin = pgn;
        cur ^= 1;
    }

    // sc MLP epilogue
    shf[w][0][bh][j] = hreg;
    __syncwarp();
    {
        float a = scb1[n * GG + j];
        #pragma unroll
        for (int k = 0; k < GG; k++)
            a = fmaf(shf[w][0][bh][k], scW1[((size_t)n * GG + k) * GG + j], a);
        shf[w][1][bh][j] = fmaxf(a, 0.0f);
    }
    __syncwarp();
    {
        float a = scb2[n * GG + j];
        #pragma unroll
        for (int k = 0; k < GG; k++)
            a = fmaf(shf[w][1][bh][k], scW2[((size_t)n * GG + k) * GG + j], a);
        shf[w][0][bh][j] = fmaxf(a, 0.0f);
    }
    __syncwarp();
    if (j == 0) {
        float q = scb3[n];
        #pragma unroll
        for (int k = 0; k < GG; k++)
            q = fmaf(shf[w][0][bh][k], scW3[n * GG + k], q);
        int idx = n * BB + bglob;
        out[idx] = out[idx] + q;   // lm kernel already wrote f
    }
}

// ============================================================================
// Kernel B: lm MLP on xl = gather(x[:, T-1]) -> WRITES f into out[n*B + b]
// ============================================================================
__global__ void __launch_bounds__(256) lm_mlp_kernel(
    const float* __restrict__ x,
    const float* __restrict__ W1, const float* __restrict__ b1,
    const float* __restrict__ W2, const float* __restrict__ b2,
    const float* __restrict__ W3, const float* __restrict__ b3,
    float* __restrict__ out)
{
    extern __shared__ __align__(16) float H1T[];      // [512][36]
    __shared__ __align__(16) float xlsT[FF][32];
    __shared__ __align__(16) float H2s[32][257];
    __shared__ float sp[8][32];

    const int n    = blockIdx.y;
    const int bblk = blockIdx.x;
    const int tid  = threadIdx.x;
    const int offs[5] = {0, -10, 1, 10, -1};

    for (int idx = tid; idx < FF * 32; idx += 256) {
        int f = idx / 32, b = idx % 32;
        int o = f / SS, sx = f % SS;
        int n2 = n + offs[o];
        float v = 0.0f;
        if (n2 >= 0 && n2 < NN) {
            size_t gb = (size_t)(bblk * 32 + b);
            v = x[(gb * TT + (TT - 1)) * (NN * SS) + n2 * SS + sx];
        }
        xlsT[f][b] = v;
    }
    __syncthreads();

    // layer 1: 8h x 8b f32x2 tile
    {
        const float* W1g = W1 + (size_t)n * FF * 512;
        const float* b1g = b1 + (size_t)n * 512;
        const int bg = tid >> 6;
        const int hg = tid & 63;
        ull acc[8][4];
        #pragma unroll
        for (int h = 0; h < 8; h++)
            #pragma unroll
            for (int p = 0; p < 4; p++) acc[h][p] = 0ULL;
        #pragma unroll 5
        for (int f = 0; f < FF; f++) {
            const float4* wv = reinterpret_cast<const float4*>(W1g + f * 512 + hg * 8);
            float4 wa = wv[0], wb = wv[1];
            ull wdp[8] = {dup2(wa.x), dup2(wa.y), dup2(wa.z), dup2(wa.w),
                          dup2(wb.x), dup2(wb.y), dup2(wb.z), dup2(wb.w)};
            const ull* xp = reinterpret_cast<const ull*>(&xlsT[f][bg * 8]);
            ull x0 = xp[0], x1 = xp[1], x2 = xp[2], x3 = xp[3];
            #pragma unroll
            for (int h = 0; h < 8; h++) {
                acc[h][0] = fma2(x0, wdp[h], acc[h][0]);
                acc[h][1] = fma2(x1, wdp[h], acc[h][1]);
                acc[h][2] = fma2(x2, wdp[h], acc[h][2]);
                acc[h][3] = fma2(x3, wdp[h], acc[h][3]);
            }
        }
        #pragma unroll
        for (int h = 0; h < 8; h++) {
            float bias = b1g[hg * 8 + h];
            float* row = &H1T[(hg * 8 + h) * FP + bg * 8];
            float4 v0, v1;
            v0.x = fmaxf(plo(acc[h][0]) + bias, 0.0f);
            v0.y = fmaxf(phi(acc[h][0]) + bias, 0.0f);
            v0.z = fmaxf(plo(acc[h][1]) + bias, 0.0f);
            v0.w = fmaxf(phi(acc[h][1]) + bias, 0.0f);
            v1.x = fmaxf(plo(acc[h][2]) + bias, 0.0f);
            v1.y = fmaxf(phi(acc[h][2]) + bias, 0.0f);
            v1.z = fmaxf(plo(acc[h][3]) + bias, 0.0f);
            v1.w = fmaxf(phi(acc[h][3]) + bias, 0.0f);
            reinterpret_cast<float4*>(row)[0] = v0;
            reinterpret_cast<float4*>(row)[1] = v1;
        }
    }
    __syncthreads();

    // layer 2: 4h x 8b f32x2 tile
    {
        const float4* W2g = reinterpret_cast<const float4*>(W2 + (size_t)n * 512 * 256);
        const float*  b2g = b2 + (size_t)n * 256;
        const int hg = tid & 63;
        const int bg = tid >> 6;
        ull acc[16];
        #pragma unroll
        for (int i = 0; i < 16; i++) acc[i] = 0ULL;
        #pragma unroll 4
        for (int f = 0; f < 512; f++) {
            float4 wv = W2g[f * 64 + hg];
            ull wdp[4] = {dup2(wv.x), dup2(wv.y), dup2(wv.z), dup2(wv.w)};
            const ull* xp = reinterpret_cast<const ull*>(&H1T[f * FP + bg * 8]);
            ull x0 = xp[0], x1 = xp[1], x2 = xp[2], x3 = xp[3];
            #pragma unroll
            for (int hh = 0; hh < 4; hh++) {
                acc[hh*4+0] = fma2(x0, wdp[hh], acc[hh*4+0]);
                acc[hh*4+1] = fma2(x1, wdp[hh], acc[hh*4+1]);
                acc[hh*4+2] = fma2(x2, wdp[hh], acc[hh*4+2]);
                acc[hh*4+3] = fma2(x3, wdp[hh], acc[hh*4+3]);
            }
        }
        #pragma unroll
        for (int hh = 0; hh < 4; hh++) {
            float bias = b2g[hg * 4 + hh];
            #pragma unroll
            for (int pi = 0; pi < 4; pi++) {
                int b = bg * 8 + pi * 2;
                H2s[b    ][hg * 4 + hh] = fmaxf(plo(acc[hh*4+pi]) + bias, 0.0f);
                H2s[b + 1][hg * 4 + hh] = fmaxf(phi(acc[hh*4+pi]) + bias, 0.0f);
            }
        }
    }
    __syncthreads();

    // layer 3
    {
        const float* W3g = W3 + (size_t)n * 256;
        int b = tid & 31, seg = tid >> 5;
        float sacc = 0.0f;
        #pragma unroll
        for (int c = 0; c < 32; c++)
            sacc = fmaf(H2s[b][seg * 32 + c], W3g[seg * 32 + c], sacc);
        sp[seg][b] = sacc;
    }
    __syncthreads();
    if (tid < 32) {
        float tot = b3[n];
        #pragma unroll
        for (int seg = 0; seg < 8; seg++) tot += sp[seg][tid];
        out[n * BB + bblk * 32 + tid] = tot;
    }
}

// ============================================================================
extern "C" void kernel_launch(void* const* d_in, const int* in_sizes, int n_in,
                              void* d_out, int out_size) {
    const float* x      = (const float*)d_in[0];
    const float* lm_W1  = (const float*)d_in[1];
    const float* lm_b1  = (const float*)d_in[2];
    const float* lm_W2  = (const float*)d_in[3];
    const float* lm_b2  = (const float*)d_in[4];
    const float* lm_W3  = (const float*)d_in[5];
    const float* lm_b3  = (const float*)d_in[6];
    const float* gWih   = (const float*)d_in[7];
    const float* gWhh   = (const float*)d_in[8];
    const float* gbih   = (const float*)d_in[9];
    const float* gbhh   = (const float*)d_in[10];
    const float* scW1   = (const float*)d_in[11];
    const float* scb1   = (const float*)d_in[12];
    const float* scW2   = (const float*)d_in[13];
    const float* scb2   = (const float*)d_in[14];
    const float* scW3   = (const float*)d_in[15];
    const float* scb3   = (const float*)d_in[16];
    float* out = (float*)d_out;

    const int h1t_bytes = 512 * FP * 4;                          // 73728
    const int a_bytes   = (35*48 + 2*35*XROW + 128*OROW) * 4;    // 69744
    cudaFuncSetAttribute(lm_mlp_kernel,
                         cudaFuncAttributeMaxDynamicSharedMemorySize, h1t_bytes);
    cudaFuncSetAttribute(gi_gemm_kernel,
                         cudaFuncAttributeMaxDynamicSharedMemorySize, a_bytes);

    // A: gi GEMM
    dim3 gridA(TT / ACH, NN), blockA(128);
    gi_gemm_kernel<<<gridA, blockA, a_bytes>>>(x, gWih);

    // B: lm MLP (writes out)
    dim3 gridB(4, NN), blockB(256);
    lm_mlp_kernel<<<gridB, blockB, h1t_bytes>>>(
        x, lm_W1, lm_b1, lm_W2, lm_b2, lm_W3, lm_b3, out);

    // C: recurrence (reads gi, adds to out)
    dim3 gridC(16, NN), blockC(128);
    gru_rec_kernel<<<gridC, blockC>>>(
        gWhh, gbih, gbhh,
        scW1, scb1, scW2, scb2, scW3, scb3, out);
}